// round 11
// baseline (speedup 1.0000x reference)
#include <cuda_runtime.h>
#include <cuda_bf16.h>
#include <cuda_fp16.h>
#include <math.h>
#include <stdint.h>

#define B_   2
#define T_   2048
#define H_   16
#define DH   64
#define DL   32
#define CDIM 1024

#define Y_ELEMS  ((size_t)B_*T_*CDIM)
#define KL_ELEMS ((size_t)B_*T_*H_*DL)

// ---- scratch ----
__device__ float g_cos[T_*DH];
__device__ float g_sin[T_*DH];

__device__ __half g_xf[(size_t)B_*T_*CDIM];
__device__ __half g_yf[(size_t)B_*T_*CDIM];
__device__ __half g_qf[(size_t)B_*T_*H_*DH];
__device__ __half g_kf[(size_t)B_*T_*H_*DH];
__device__ __half g_vf[(size_t)B_*T_*H_*DH];
__device__ __half g_wf[3u*1024*1024];
#define WQ_OFF 0u
#define WK_OFF (1024u*1024u)
#define WV_OFF (1536u*1024u)
#define WC_OFF (2048u*1024u)

// ============================================================
// PTX helpers
// ============================================================
__device__ __forceinline__ uint32_t smem_u32(const void* p) {
    uint32_t a;
    asm("{ .reg .u64 t; cvta.to.shared.u64 t, %1; cvt.u32.u64 %0, t; }"
        : "=r"(a) : "l"(p));
    return a;
}
__device__ __forceinline__ void bulk_cp(uint32_t dst, const void* src,
                                        uint32_t bytes, uint32_t mbar) {
    asm volatile(
        "cp.async.bulk.shared::cluster.global.mbarrier::complete_tx::bytes "
        "[%0], [%1], %2, [%3];"
        :: "r"(dst), "l"(src), "r"(bytes), "r"(mbar) : "memory");
}
#define MBARRIER_INIT(addr, cnt) \
    asm volatile("mbarrier.init.shared.b64 [%0], %1;" :: "r"(addr), "r"(cnt) : "memory")
#define MBARRIER_EXPECT_TX(addr, bytes) \
    asm volatile("mbarrier.arrive.expect_tx.shared.b64 _, [%0], %1;" \
                 :: "r"(addr), "r"(bytes) : "memory")
#define MBARRIER_WAIT_PARITY(addr, parity) do {                                  \
    uint32_t _mb = (uint32_t)(addr);                                             \
    uint32_t _pa = (uint32_t)(parity);                                           \
    uint32_t _done;                                                              \
    asm volatile("{\n .reg .pred p;\n"                                           \
        " mbarrier.try_wait.parity.acquire.cta.shared::cta.b64 p, [%1], %2;\n"   \
        " selp.b32 %0, 1, 0, p;\n}"                                              \
        : "=r"(_done) : "r"(_mb), "r"(_pa) : "memory");                          \
    if (!_done) {                                                                \
        asm volatile("{\n .reg .pred P1;\n"                                      \
            "WL_%=:\n"                                                           \
            " mbarrier.try_wait.parity.acquire.cta.shared::cta.b64 P1, [%0], %1, 0x989680;\n" \
            " @P1 bra.uni WD_%=;\n bra.uni WL_%=;\n WD_%=:\n}"                   \
            :: "r"(_mb), "r"(_pa) : "memory");                                   \
    }                                                                            \
} while (0)

__device__ __forceinline__ void ldm_x4(uint32_t* r, uint32_t addr) {
    asm volatile("ldmatrix.sync.aligned.m8n8.x4.shared.b16 {%0,%1,%2,%3}, [%4];"
        : "=r"(r[0]), "=r"(r[1]), "=r"(r[2]), "=r"(r[3]) : "r"(addr));
}
__device__ __forceinline__ void ldm_x4_t(uint32_t* r, uint32_t addr) {
    asm volatile("ldmatrix.sync.aligned.m8n8.x4.trans.shared.b16 {%0,%1,%2,%3}, [%4];"
        : "=r"(r[0]), "=r"(r[1]), "=r"(r[2]), "=r"(r[3]) : "r"(addr));
}
__device__ __forceinline__ void mma_f16(float* c, const uint32_t* a, const uint32_t* b) {
    asm volatile("mma.sync.aligned.m16n8k16.row.col.f32.f16.f16.f32 "
        "{%0,%1,%2,%3}, {%4,%5,%6,%7}, {%8,%9}, {%0,%1,%2,%3};\n"
        : "+f"(c[0]), "+f"(c[1]), "+f"(c[2]), "+f"(c[3])
        : "r"(a[0]), "r"(a[1]), "r"(a[2]), "r"(a[3]), "r"(b[0]), "r"(b[1]));
}
__device__ __forceinline__ uint32_t pack_h2(float a, float b) {
    __half2 h = __floats2half2_rn(a, b);
    return *(uint32_t*)&h;
}

// ============================================================
// fp32 -> fp16 convert kernels
// ============================================================
__global__ void __launch_bounds__(256)
cvt_x_kernel(const float* __restrict__ in)
{
    int i = blockIdx.x * blockDim.x + threadIdx.x;
    float4 v = ((const float4*)in)[i];
    ((uint32_t*)g_xf)[2*i]   = pack_h2(v.x, v.y);
    ((uint32_t*)g_xf)[2*i+1] = pack_h2(v.z, v.w);
}

__global__ void __launch_bounds__(256)
cvt_w_kernel(const float* __restrict__ Wq, const float* __restrict__ Wk,
             const float* __restrict__ Wv, const float* __restrict__ Wc)
{
    int i = blockIdx.x * blockDim.x + threadIdx.x;
    const float* src; int off;
    if      (i < 262144) { src = Wq; off = i; }
    else if (i < 393216) { src = Wk; off = i - 262144; }
    else if (i < 524288) { src = Wv; off = i - 393216; }
    else                 { src = Wc; off = i - 524288; }
    float4 v = ((const float4*)src)[off];
    ((uint32_t*)g_wf)[2*i]   = pack_h2(v.x, v.y);
    ((uint32_t*)g_wf)[2*i+1] = pack_h2(v.z, v.w);
}

// ============================================================
// fp16 HMMA GEMM, bulk-copy + mbarrier pipeline.
// K-chunk 64, 3 stages, 2 CTAs/SM. A:[M,K], W:[N,K] fp16.
// ============================================================
#define GS_ROWB   144
#define GS_MAT    (128 * GS_ROWB)       // 18432
#define GS_STAGE  (2 * GS_MAT)          // 36864 (A, B)
#define GS_MBAR   (3 * GS_STAGE)        // 110592
#define GS_SMEM   (GS_MBAR + 64)

__device__ __forceinline__ void hgemm_issue(
    const __half* __restrict__ A, const __half* __restrict__ B,
    int K, int bm, int bn, int k0, uint32_t sbase, uint32_t mbar, int lane)
{
    if (lane == 0) MBARRIER_EXPECT_TX(mbar, 32768);
    __syncwarp();
#pragma unroll
    for (int j = 0; j < 8; j++) {
        int task = (j << 5) + lane;          // 0..255
        int row  = task & 127;
        int isB  = task >> 7;
        const __half* base = isB ? B : A;
        int grow = (isB ? bn : bm) + row;
        bulk_cp(sbase + isB * GS_MAT + row * GS_ROWB,
                base + (size_t)grow * K + k0, 128, mbar);
    }
}

__device__ __forceinline__ void hgemm_body(
    const __half* __restrict__ A, const __half* __restrict__ B,
    float* __restrict__ C, int K, int N, int bm, int bn, int mode)
{
    extern __shared__ __align__(128) char sm[];
    const uint32_t smb = smem_u32(sm);
    const uint32_t mb0 = smb + GS_MBAR;
    const int tid  = threadIdx.x;
    const int wid  = tid >> 5;
    const int lane = tid & 31;
    const int wm = (wid >> 2) << 6;
    const int wn = (wid & 3) << 5;

    const int rA = (lane & 7) + ((lane >> 3) & 1) * 8;
    const int cA = (lane >> 4) << 3;
    const int rB = (lane & 7) + ((lane >> 4) << 3);
    const int cB = ((lane >> 3) & 1) << 3;

    float acc[4][4][4];
#pragma unroll
    for (int mt = 0; mt < 4; mt++)
#pragma unroll
        for (int nt = 0; nt < 4; nt++)
#pragma unroll
            for (int e = 0; e < 4; e++) acc[mt][nt][e] = 0.f;

    const int NC = K >> 6;

    if (tid == 0) {
        MBARRIER_INIT(mb0,      1);
        MBARRIER_INIT(mb0 + 8,  1);
        MBARRIER_INIT(mb0 + 16, 1);
    }
    __syncthreads();
    if (wid == 0) {
        hgemm_issue(A, B, K, bm, bn, 0,  smb,            mb0,     lane);
        hgemm_issue(A, B, K, bm, bn, 64, smb + GS_STAGE, mb0 + 8, lane);
    }

    int ph0 = 0, ph1 = 0, ph2 = 0;
    int st = 0;
    for (int c = 0; c < NC; c++) {
        int ph = (st == 0) ? ph0 : (st == 1) ? ph1 : ph2;
        MBARRIER_WAIT_PARITY(mb0 + 8 * st, ph);
        if      (st == 0) ph0 ^= 1;
        else if (st == 1) ph1 ^= 1;
        else              ph2 ^= 1;
        const uint32_t sb = smb + st * GS_STAGE;

#pragma unroll
        for (int ks = 0; ks < 4; ks++) {
            const int k0 = ks << 4;
            uint32_t af[4][4], bf[2][4];
#pragma unroll
            for (int mt = 0; mt < 4; mt++) {
                uint32_t ro = (uint32_t)(wm + (mt << 4) + rA) * GS_ROWB + ((k0 + cA) << 1);
                ldm_x4(af[mt], sb + ro);
            }
#pragma unroll
            for (int nt2 = 0; nt2 < 2; nt2++) {
                uint32_t ro = (uint32_t)(wn + (nt2 << 4) + rB) * GS_ROWB + ((k0 + cB) << 1);
                ldm_x4(bf[nt2], sb + GS_MAT + ro);
            }
#pragma unroll
            for (int mt = 0; mt < 4; mt++)
#pragma unroll
                for (int nt = 0; nt < 4; nt++)
                    mma_f16(acc[mt][nt], af[mt], &bf[nt >> 1][(nt & 1) << 1]);
        }

        __syncthreads();
        if (wid == 0 && c + 2 < NC) {
            int s2 = st + 2; if (s2 >= 3) s2 -= 3;
            hgemm_issue(A, B, K, bm, bn, (c + 2) << 6,
                        smb + s2 * GS_STAGE, mb0 + 8 * s2, lane);
        }
        st = (st + 1 == 3) ? 0 : st + 1;
    }

    const int g  = lane >> 2;
    const int tg = lane & 3;
    if (mode == 0) {
#pragma unroll
        for (int mt = 0; mt < 4; mt++) {
            const int row0 = bm + wm + (mt << 4) + g;
#pragma unroll
            for (int nt = 0; nt < 4; nt++) {
                const int col = bn + wn + (nt << 3) + (tg << 1);
                *(float2*)&C[(size_t)row0 * N + col] =
                    make_float2(acc[mt][nt][0], acc[mt][nt][1]);
                *(float2*)&C[(size_t)(row0 + 8) * N + col] =
                    make_float2(acc[mt][nt][2], acc[mt][nt][3]);
            }
        }
    } else {
        // rope + 0.125 scale -> g_qf (fp16)
#pragma unroll
        for (int mt = 0; mt < 4; mt++) {
            const int row0 = bm + wm + (mt << 4) + g;
            const int t0 = row0 & (T_ - 1);
            const int t1 = (row0 + 8) & (T_ - 1);
#pragma unroll
            for (int nt = 0; nt < 4; nt++) {
                const int col = bn + wn + (nt << 3) + (tg << 1);
                const int d0 = col & 63, d1 = d0 + 1;
                float q0 = acc[mt][nt][0] * 0.125f, q1 = acc[mt][nt][1] * 0.125f;
                float c0 = g_cos[t0*DH+d0], s0 = g_sin[t0*DH+d0];
                float c1 = g_cos[t0*DH+d1], s1 = g_sin[t0*DH+d1];
                ((uint32_t*)g_qf)[((size_t)row0 * CDIM + col) >> 1] =
                    pack_h2(q0*c0 - q1*s0, q1*c1 + q0*s1);
                q0 = acc[mt][nt][2] * 0.125f; q1 = acc[mt][nt][3] * 0.125f;
                c0 = g_cos[t1*DH+d0]; s0 = g_sin[t1*DH+d0];
                c1 = g_cos[t1*DH+d1]; s1 = g_sin[t1*DH+d1];
                ((uint32_t*)g_qf)[((size_t)(row0 + 8) * CDIM + col) >> 1] =
                    pack_h2(q0*c0 - q1*s0, q1*c1 + q0*s1);
            }
        }
    }
}

__global__ void __launch_bounds__(256, 2)
proj_gemm(const __half* __restrict__ xf, const __half* __restrict__ wf,
          float* __restrict__ Ck, float* __restrict__ Cv)
{
    const int bm = blockIdx.y << 7;
    if (blockIdx.z == 0) {
        hgemm_body(xf, wf + WQ_OFF, nullptr, CDIM, CDIM, bm, blockIdx.x << 7, 1);
    } else if (blockIdx.x < 4) {
        hgemm_body(xf, wf + WK_OFF, Ck, CDIM, 512, bm, blockIdx.x << 7, 0);
    } else {
        hgemm_body(xf, wf + WV_OFF, Cv, CDIM, 512, bm, (blockIdx.x - 4) << 7, 0);
    }
}

__global__ void __launch_bounds__(256, 2)
hgemm_wc(const __half* __restrict__ A, const __half* __restrict__ B,
         float* __restrict__ C)
{
    hgemm_body(A, B, C, CDIM, CDIM, blockIdx.y << 7, blockIdx.x << 7, 0);
}

// ============================================================
// RoPE table
// ============================================================
__global__ void rope_table_kernel() {
    int t = blockIdx.x;
    int c = threadIdx.x;
    int j = c & 31;
    double inv = pow(10000.0, -(double)j / 32.0);
    float  ang = (float)t * (float)inv;
    double s, cc;
    sincos((double)ang, &s, &cc);
    g_cos[t * DH + c] = (float)cc;
    g_sin[t * DH + c] = (float)s;
}

// ============================================================
// Up-projection + RoPE for k, v -> fp16. 4 tokens per CTA.
// ============================================================
__global__ void __launch_bounds__(256)
upproj_rope_kernel(const float* __restrict__ klat, const float* __restrict__ vlat,
                   const float* __restrict__ Wku,  const float* __restrict__ Wvu)
{
    const int bt0 = blockIdx.x << 2;
    __shared__ float skl[2048], svl[2048];
    __shared__ float swk[64 * 33], swv[64 * 33];
    const int tid = threadIdx.x;

    for (int u = tid; u < 512; u += 256) {
        ((float4*)skl)[u] = ((const float4*)(klat + (size_t)bt0 * 512))[u];
        ((float4*)svl)[u] = ((const float4*)(vlat + (size_t)bt0 * 512))[u];
    }
    for (int i = tid; i < 64 * 32; i += 256) {
        int d = i >> 5, l = i & 31;
        swk[d * 33 + l] = Wku[i];
        swv[d * 33 + l] = Wvu[i];
    }
    __syncthreads();

#pragma unroll
    for (int u = 0; u < 8; u++) {
        const int unit = tid + (u << 8);
        const int tok = unit >> 9;
        const int p   = unit & 511;
        const int h  = p >> 5, i = p & 31;
        const int d0 = i << 1, d1 = d0 + 1;
        const int bt = bt0 + tok;
        const int t  = bt & (T_ - 1);
        const float* kl  = &skl[(tok << 9) + (h << 5)];
        const float* vl  = &svl[(tok << 9) + (h << 5)];
        const float* wk0 = &swk[d0 * 33];
        const float* wk1 = &swk[d1 * 33];
        const float* wv0 = &swv[d0 * 33];
        const float* wv1 = &swv[d1 * 33];
        float k0 = 0.f, k1 = 0.f, v0 = 0.f, v1 = 0.f;
#pragma unroll
        for (int l = 0; l < 32; l++) {
            float klv = kl[l], vlv = vl[l];
            k0 = fmaf(klv, wk0[l], k0);
            k1 = fmaf(klv, wk1[l], k1);
            v0 = fmaf(vlv, wv0[l], v0);
            v1 = fmaf(vlv, wv1[l], v1);
        }
        const float c0 = g_cos[t * DH + d0], s0 = g_sin[t * DH + d0];
        const float c1 = g_cos[t * DH + d1], s1 = g_sin[t * DH + d1];
        const size_t pi = (((size_t)bt * H_ + h) * DH + d0) >> 1;
        ((uint32_t*)g_kf)[pi] = pack_h2(k0 * c0 - k1 * s0, k1 * c1 + k0 * s1);
        ((uint32_t*)g_vf)[pi] = pack_h2(v0, v1);
    }
}

// ============================================================
// fp16 HMMA causal flash attention, bulk-copy + mbarrier KV
// pipeline (3 stages), 2 CTAs/SM.
// ============================================================
#define AT_ROWB   144
#define AT_MAT    (64 * AT_ROWB)        // 9216
#define AT_STAGE  (2 * AT_MAT)          // 18432 (K, V)
#define AT_QOFF   (3 * AT_STAGE)        // 55296
#define AT_QMAT   (128 * AT_ROWB)       // 18432
#define AT_MBAR   (AT_QOFF + AT_QMAT)   // 73728: full0,full1,full2,qbar
#define AT_SMEM   (AT_MBAR + 64)

__device__ __forceinline__ void attn_issue_kv(int b, int h, int kb,
                                              uint32_t sbase, uint32_t mbar, int lane)
{
    if (lane == 0) MBARRIER_EXPECT_TX(mbar, 16384);
    __syncwarp();
    const int k0 = kb << 6;
#pragma unroll
    for (int j = 0; j < 4; j++) {
        int task = (j << 5) + lane;      // 0..127
        int row = task & 63;
        int isV = task >> 6;
        const __half* base = isV ? g_vf : g_kf;
        const void* src = base + ((size_t)(b * T_ + k0 + row) * H_ + h) * DH;
        bulk_cp(sbase + isV * AT_MAT + row * AT_ROWB, src, 128, mbar);
    }
}

__global__ void __launch_bounds__(256, 2)
attn_mma_kernel()
{
    extern __shared__ __align__(128) char sm[];
    const uint32_t smb = smem_u32(sm);
    const uint32_t mb0 = smb + AT_MBAR;
    const int tid = threadIdx.x;
    const int wid = tid >> 5, lane = tid & 31;
    const int qt = gridDim.x - 1 - blockIdx.x;
    const int h = blockIdx.y, b = blockIdx.z;
    const int q0 = qt << 7;
    const int nkb = 2 * qt + 2;
    const int g = lane >> 2, tg = lane & 3;

    if (tid == 0) {
        MBARRIER_INIT(mb0,      1);
        MBARRIER_INIT(mb0 + 8,  1);
        MBARRIER_INIT(mb0 + 16, 1);
        MBARRIER_INIT(mb0 + 24, 1);
    }
    __syncthreads();
    if (wid == 0) {
        // Q tile (128 rows)
        if (lane == 0) MBARRIER_EXPECT_TX(mb0 + 24, 16384);
        __syncwarp();
#pragma unroll
        for (int j = 0; j < 4; j++) {
            int row = (j << 5) + lane;
            const void* src = g_qf + ((size_t)(b * T_ + q0 + row) * H_ + h) * DH;
            bulk_cp(smb + AT_QOFF + row * AT_ROWB, src, 128, mb0 + 24);
        }
        attn_issue_kv(b, h, 0, smb,            mb0,     lane);
        attn_issue_kv(b, h, 1, smb + AT_STAGE, mb0 + 8, lane);
    }

    // Q fragments (persistent)
    MBARRIER_WAIT_PARITY(mb0 + 24, 0);
    const int rA = (lane & 7) + ((lane >> 3) & 1) * 8;
    const int cA = (lane >> 4) << 3;
    uint32_t qf[4][4];
#pragma unroll
    for (int kf = 0; kf < 4; kf++) {
        uint32_t ro = (uint32_t)(wid * 16 + rA) * AT_ROWB + ((kf * 16 + cA) << 1);
        ldm_x4(qf[kf], smb + AT_QOFF + ro);
    }

    const int rB = (lane & 7) + ((lane >> 4) << 3);
    const int cB = ((lane >> 3) & 1) << 3;
    const int rV = lane & 15;
    const int cV = (lane >> 4) << 4;

    float yacc[8][4];
#pragma unroll
    for (int i = 0; i < 8; i++)
#pragma unroll
        for (int e = 0; e < 4; e++) yacc[i][e] = 0.f;
    float m0 = -1e30f, m1 = -1e30f, l0 = 0.f, l1 = 0.f;

    int ph0 = 0, ph1 = 0, ph2 = 0;
    int st = 0;
    for (int kb = 0; kb < nkb; kb++) {
        int ph = (st == 0) ? ph0 : (st == 1) ? ph1 : ph2;
        MBARRIER_WAIT_PARITY(mb0 + 8 * st, ph);
        if      (st == 0) ph0 ^= 1;
        else if (st == 1) ph1 ^= 1;
        else              ph2 ^= 1;
        const uint32_t sb = smb + st * AT_STAGE;

        // ---- S = Q K^T ----
        float s[8][4];
#pragma unroll
        for (int i = 0; i < 8; i++)
#pragma unroll
            for (int e = 0; e < 4; e++) s[i][e] = 0.f;
#pragma unroll
        for (int kf = 0; kf < 4; kf++) {
#pragma unroll
            for (int nt16 = 0; nt16 < 4; nt16++) {
                uint32_t ro = (uint32_t)(nt16 * 16 + rB) * AT_ROWB + ((kf * 16 + cB) << 1);
                uint32_t bk[4];
                ldm_x4(bk, sb + ro);
                mma_f16(s[nt16 * 2],     qf[kf], &bk[0]);
                mma_f16(s[nt16 * 2 + 1], qf[kf], &bk[2]);
            }
        }

        // ---- causal mask (diagonal blocks only) ----
        if (kb >= 2 * qt) {
            const int row0 = q0 + wid * 16 + g;
#pragma unroll
            for (int nt = 0; nt < 8; nt++) {
                const int col0 = (kb << 6) + nt * 8 + (tg << 1);
                if (col0     > row0)     s[nt][0] = -1e30f;
                if (col0 + 1 > row0)     s[nt][1] = -1e30f;
                if (col0     > row0 + 8) s[nt][2] = -1e30f;
                if (col0 + 1 > row0 + 8) s[nt][3] = -1e30f;
            }
        }

        // ---- online softmax (fp32) ----
        float mx0 = -1e30f, mx1 = -1e30f;
#pragma unroll
        for (int nt = 0; nt < 8; nt++) {
            mx0 = fmaxf(mx0, fmaxf(s[nt][0], s[nt][1]));
            mx1 = fmaxf(mx1, fmaxf(s[nt][2], s[nt][3]));
        }
        mx0 = fmaxf(mx0, __shfl_xor_sync(0xffffffffu, mx0, 1));
        mx0 = fmaxf(mx0, __shfl_xor_sync(0xffffffffu, mx0, 2));
        mx1 = fmaxf(mx1, __shfl_xor_sync(0xffffffffu, mx1, 1));
        mx1 = fmaxf(mx1, __shfl_xor_sync(0xffffffffu, mx1, 2));
        const float mn0 = fmaxf(m0, mx0), mn1 = fmaxf(m1, mx1);
        const float a0 = __expf(m0 - mn0), a1 = __expf(m1 - mn1);
        m0 = mn0; m1 = mn1;
        float r0 = 0.f, r1 = 0.f;
#pragma unroll
        for (int nt = 0; nt < 8; nt++) {
            s[nt][0] = __expf(s[nt][0] - mn0);
            s[nt][1] = __expf(s[nt][1] - mn0);
            s[nt][2] = __expf(s[nt][2] - mn1);
            s[nt][3] = __expf(s[nt][3] - mn1);
            r0 += s[nt][0] + s[nt][1];
            r1 += s[nt][2] + s[nt][3];
        }
        r0 += __shfl_xor_sync(0xffffffffu, r0, 1);
        r0 += __shfl_xor_sync(0xffffffffu, r0, 2);
        r1 += __shfl_xor_sync(0xffffffffu, r1, 1);
        r1 += __shfl_xor_sync(0xffffffffu, r1, 2);
        l0 = l0 * a0 + r0;
        l1 = l1 * a1 + r1;
#pragma unroll
        for (int i = 0; i < 8; i++) {
            yacc[i][0] *= a0; yacc[i][1] *= a0;
            yacc[i][2] *= a1; yacc[i][3] *= a1;
        }

        // ---- O += P V ----
#pragma unroll
        for (int kf = 0; kf < 4; kf++) {
            uint32_t phh[4];
            phh[0] = pack_h2(s[2*kf][0],   s[2*kf][1]);
            phh[1] = pack_h2(s[2*kf][2],   s[2*kf][3]);
            phh[2] = pack_h2(s[2*kf+1][0], s[2*kf+1][1]);
            phh[3] = pack_h2(s[2*kf+1][2], s[2*kf+1][3]);
#pragma unroll
            for (int dt = 0; dt < 4; dt++) {
                uint32_t vh[4];
                uint32_t ro = (uint32_t)(kf * 16 + rV) * AT_ROWB + dt * 32 + cV;
                ldm_x4_t(vh, sb + AT_MAT + ro);
                mma_f16(yacc[dt * 2],     phh, &vh[0]);
                mma_f16(yacc[dt * 2 + 1], phh, &vh[2]);
            }
        }

        __syncthreads();
        if (wid == 0 && kb + 2 < nkb) {
            int s2 = st + 2; if (s2 >= 3) s2 -= 3;
            attn_issue_kv(b, h, kb + 2, smb + s2 * AT_STAGE, mb0 + 8 * s2, lane);
        }
        st = (st + 1 == 3) ? 0 : st + 1;
    }

    // epilogue: fp16 y for Wc GEMM
    const float il0 = 1.f / l0, il1 = 1.f / l1;
    const int row0 = q0 + wid * 16 + g;
#pragma unroll
    for (int dt8 = 0; dt8 < 8; dt8++) {
        const int col = h * 64 + dt8 * 8 + (tg << 1);
        ((uint32_t*)g_yf)[((size_t)(b * T_ + row0) * CDIM + col) >> 1] =
            pack_h2(yacc[dt8][0] * il0, yacc[dt8][1] * il0);
        ((uint32_t*)g_yf)[((size_t)(b * T_ + row0 + 8) * CDIM + col) >> 1] =
            pack_h2(yacc[dt8][2] * il1, yacc[dt8][3] * il1);
    }
}

// ============================================================
// launch
// ============================================================
extern "C" void kernel_launch(void* const* d_in, const int* in_sizes, int n_in,
                              void* d_out, int out_size)
{
    const float* x   = (const float*)d_in[0];
    const float* Wq  = (const float*)d_in[1];
    const float* Wk  = (const float*)d_in[2];
    const float* Wv  = (const float*)d_in[3];
    const float* Wku = (const float*)d_in[4];
    const float* Wvu = (const float*)d_in[5];
    const float* Wc  = (const float*)d_in[6];

    float* out      = (float*)d_out;
    float* y_out    = out;
    float* klat_out = out + Y_ELEMS;
    float* vlat_out = out + Y_ELEMS + KL_ELEMS;

    __half *xf, *yf, *wf;
    cudaGetSymbolAddress((void**)&xf, g_xf);
    cudaGetSymbolAddress((void**)&yf, g_yf);
    cudaGetSymbolAddress((void**)&wf, g_wf);

    cudaFuncSetAttribute(attn_mma_kernel, cudaFuncAttributeMaxDynamicSharedMemorySize, AT_SMEM);
    cudaFuncSetAttribute(proj_gemm, cudaFuncAttributeMaxDynamicSharedMemorySize, GS_SMEM);
    cudaFuncSetAttribute(hgemm_wc, cudaFuncAttributeMaxDynamicSharedMemorySize, GS_SMEM);

    rope_table_kernel<<<T_, 64>>>();
    cvt_x_kernel<<<4096, 256>>>(x);
    cvt_w_kernel<<<3072, 256>>>(Wq, Wk, Wv, Wc);

    dim3 gp(8, (B_ * T_) / 128, 2);
    proj_gemm<<<gp, 256, GS_SMEM>>>(xf, wf, klat_out, vlat_out);

    upproj_rope_kernel<<<B_ * T_ / 4, 256>>>(klat_out, vlat_out, Wku, Wvu);

    dim3 ga(T_ / 128, H_, B_);
    attn_mma_kernel<<<ga, 256, AT_SMEM>>>();

    dim3 gc(8, (B_ * T_) / 128);
    hgemm_wc<<<gc, 256, GS_SMEM>>>(yf, wf + WC_OFF, y_out);
}

// round 12
// speedup vs baseline: 2.5324x; 2.5324x over previous
#include <cuda_runtime.h>
#include <cuda_bf16.h>
#include <cuda_fp16.h>
#include <math.h>
#include <stdint.h>

#define B_   2
#define T_   2048
#define H_   16
#define DH   64
#define DL   32
#define CDIM 1024

#define Y_ELEMS  ((size_t)B_*T_*CDIM)
#define KL_ELEMS ((size_t)B_*T_*H_*DL)

// ---- scratch ----
__device__ float g_cos[T_*DH];
__device__ float g_sin[T_*DH];

__device__ __half g_xf[(size_t)B_*T_*CDIM];
__device__ __half g_yf[(size_t)B_*T_*CDIM];
__device__ __half g_qf[(size_t)B_*T_*H_*DH];
__device__ __half g_kf[(size_t)B_*T_*H_*DH];
__device__ __half g_vf[(size_t)B_*T_*H_*DH];
__device__ __half g_wf[3u*1024*1024];
#define WQ_OFF 0u
#define WK_OFF (1024u*1024u)
#define WV_OFF (1536u*1024u)
#define WC_OFF (2048u*1024u)

// ============================================================
// PTX helpers
// ============================================================
__device__ __forceinline__ uint32_t smem_u32(const void* p) {
    uint32_t a;
    asm("{ .reg .u64 t; cvta.to.shared.u64 t, %1; cvt.u32.u64 %0, t; }"
        : "=r"(a) : "l"(p));
    return a;
}
__device__ __forceinline__ void cp16(uint32_t dst, const void* src) {
    asm volatile("cp.async.cg.shared.global [%0], [%1], 16;\n"
                 :: "r"(dst), "l"(src));
}
__device__ __forceinline__ void cp_commit() {
    asm volatile("cp.async.commit_group;\n" ::: "memory");
}
template<int N> __device__ __forceinline__ void cp_wait() {
    asm volatile("cp.async.wait_group %0;\n" :: "n"(N) : "memory");
}
__device__ __forceinline__ void ldm_x4(uint32_t* r, uint32_t addr) {
    asm volatile("ldmatrix.sync.aligned.m8n8.x4.shared.b16 {%0,%1,%2,%3}, [%4];"
        : "=r"(r[0]), "=r"(r[1]), "=r"(r[2]), "=r"(r[3]) : "r"(addr));
}
__device__ __forceinline__ void ldm_x4_t(uint32_t* r, uint32_t addr) {
    asm volatile("ldmatrix.sync.aligned.m8n8.x4.trans.shared.b16 {%0,%1,%2,%3}, [%4];"
        : "=r"(r[0]), "=r"(r[1]), "=r"(r[2]), "=r"(r[3]) : "r"(addr));
}
__device__ __forceinline__ void mma_f16(float* c, const uint32_t* a, const uint32_t* b) {
    asm volatile("mma.sync.aligned.m16n8k16.row.col.f32.f16.f16.f32 "
        "{%0,%1,%2,%3}, {%4,%5,%6,%7}, {%8,%9}, {%0,%1,%2,%3};\n"
        : "+f"(c[0]), "+f"(c[1]), "+f"(c[2]), "+f"(c[3])
        : "r"(a[0]), "r"(a[1]), "r"(a[2]), "r"(a[3]), "r"(b[0]), "r"(b[1]));
}
__device__ __forceinline__ uint32_t pack_h2(float a, float b) {
    __half2 h = __floats2half2_rn(a, b);
    return *(uint32_t*)&h;
}

// ============================================================
// prep: cvt x, cvt weights, rope table — one launch
// blocks [0,4096) cvt_x; [4096,7168) cvt_w; [7168,7680) rope
// ============================================================
__global__ void __launch_bounds__(256)
prep_kernel(const float* __restrict__ x,
            const float* __restrict__ Wq, const float* __restrict__ Wk,
            const float* __restrict__ Wv, const float* __restrict__ Wc)
{
    const int bid = blockIdx.x;
    const int tid = threadIdx.x;
    if (bid < 4096) {
        int i = bid * 256 + tid;
        float4 v = ((const float4*)x)[i];
        ((uint32_t*)g_xf)[2*i]   = pack_h2(v.x, v.y);
        ((uint32_t*)g_xf)[2*i+1] = pack_h2(v.z, v.w);
    } else if (bid < 7168) {
        int i = (bid - 4096) * 256 + tid;
        const float* src; int off;
        if      (i < 262144) { src = Wq; off = i; }
        else if (i < 393216) { src = Wk; off = i - 262144; }
        else if (i < 524288) { src = Wv; off = i - 393216; }
        else                 { src = Wc; off = i - 524288; }
        float4 v = ((const float4*)src)[off];
        ((uint32_t*)g_wf)[2*i]   = pack_h2(v.x, v.y);
        ((uint32_t*)g_wf)[2*i+1] = pack_h2(v.z, v.w);
    } else {
        int t = (bid - 7168) * 4 + (tid >> 6);
        int c = tid & 63;
        int j = c & 31;
        double inv = pow(10000.0, -(double)j / 32.0);
        float  ang = (float)t * (float)inv;
        double s, cc;
        sincos((double)ang, &s, &cc);
        g_cos[t * DH + c] = (float)cc;
        g_sin[t * DH + c] = (float)s;
    }
}

// ============================================================
// fp16 HMMA GEMM: K-chunk 64, 2-stage double buffer, 2 CTAs/SM.
// A:[M,K] fp16, W:[N,K] fp16 (K-contig). 144B rows (conflict-free).
// ============================================================
#define GS_ROWB   144
#define GS_MAT    (128 * GS_ROWB)       // 18432
#define GS_STAGE  (2 * GS_MAT)          // 36864 (A, B)
#define GS_SMEM   (2 * GS_STAGE)        // 73728 -> 2 CTAs/SM

__device__ __forceinline__ void hgemm_load_chunk(
    const __half* __restrict__ A, const __half* __restrict__ B,
    int K, int bm, int bn, int k0, uint32_t sbase, int tid)
{
#pragma unroll
    for (int i = 0; i < 8; i++) {
        int task = tid + (i << 8);      // 2048: op(2) x row(128) x granule(8)
        int op   = task >> 10;
        int t2   = task & 1023;
        int row  = t2 >> 3;
        int g    = t2 & 7;
        const __half* base = op ? B : A;
        int grow = (op ? bn : bm) + row;
        const void* src = base + (size_t)grow * K + k0 + (g << 3);
        uint32_t dst = sbase + op * GS_MAT + row * GS_ROWB + (g << 4);
        cp16(dst, src);
    }
}

__device__ __forceinline__ void hgemm_body(
    const __half* __restrict__ A, const __half* __restrict__ B,
    float* __restrict__ C, int K, int N, int bm, int bn, int mode)
{
    extern __shared__ __align__(128) char sm[];
    const uint32_t smb = smem_u32(sm);
    const int tid  = threadIdx.x;
    const int wid  = tid >> 5;
    const int lane = tid & 31;
    const int wm = (wid >> 2) << 6;
    const int wn = (wid & 3) << 5;

    const int rA = (lane & 7) + ((lane >> 3) & 1) * 8;
    const int cA = (lane >> 4) << 3;
    const int rB = (lane & 7) + ((lane >> 4) << 3);
    const int cB = ((lane >> 3) & 1) << 3;

    float acc[4][4][4];
#pragma unroll
    for (int mt = 0; mt < 4; mt++)
#pragma unroll
        for (int nt = 0; nt < 4; nt++)
#pragma unroll
            for (int e = 0; e < 4; e++) acc[mt][nt][e] = 0.f;

    const int NC = K >> 6;              // chunks of 64

    hgemm_load_chunk(A, B, K, bm, bn, 0, smb, tid);
    cp_commit();
    hgemm_load_chunk(A, B, K, bm, bn, 64, smb + GS_STAGE, tid);
    cp_commit();

    for (int c = 0; c < NC; c++) {
        const uint32_t sb = smb + (c & 1) * GS_STAGE;
        if (c + 1 < NC) cp_wait<1>(); else cp_wait<0>();
        __syncthreads();

#pragma unroll
        for (int ks = 0; ks < 4; ks++) {
            const int k0 = ks << 4;
            uint32_t af[4][4], bf[2][4];
#pragma unroll
            for (int mt = 0; mt < 4; mt++) {
                uint32_t ro = (uint32_t)(wm + (mt << 4) + rA) * GS_ROWB + ((k0 + cA) << 1);
                ldm_x4(af[mt], sb + ro);
            }
#pragma unroll
            for (int nt2 = 0; nt2 < 2; nt2++) {
                uint32_t ro = (uint32_t)(wn + (nt2 << 4) + rB) * GS_ROWB + ((k0 + cB) << 1);
                ldm_x4(bf[nt2], sb + GS_MAT + ro);
            }
#pragma unroll
            for (int mt = 0; mt < 4; mt++)
#pragma unroll
                for (int nt = 0; nt < 4; nt++)
                    mma_f16(acc[mt][nt], af[mt], &bf[nt >> 1][(nt & 1) << 1]);
        }

        __syncthreads();
        if (c + 2 < NC)
            hgemm_load_chunk(A, B, K, bm, bn, (c + 2) << 6,
                             smb + (c & 1) * GS_STAGE, tid);
        cp_commit();
    }

    const int g  = lane >> 2;
    const int tg = lane & 3;
    if (mode == 0) {
#pragma unroll
        for (int mt = 0; mt < 4; mt++) {
            const int row0 = bm + wm + (mt << 4) + g;
#pragma unroll
            for (int nt = 0; nt < 4; nt++) {
                const int col = bn + wn + (nt << 3) + (tg << 1);
                *(float2*)&C[(size_t)row0 * N + col] =
                    make_float2(acc[mt][nt][0], acc[mt][nt][1]);
                *(float2*)&C[(size_t)(row0 + 8) * N + col] =
                    make_float2(acc[mt][nt][2], acc[mt][nt][3]);
            }
        }
    } else {
        // rope + 0.125 scale -> g_qf (fp16)
#pragma unroll
        for (int mt = 0; mt < 4; mt++) {
            const int row0 = bm + wm + (mt << 4) + g;
            const int t0 = row0 & (T_ - 1);
            const int t1 = (row0 + 8) & (T_ - 1);
#pragma unroll
            for (int nt = 0; nt < 4; nt++) {
                const int col = bn + wn + (nt << 3) + (tg << 1);
                const int d0 = col & 63, d1 = d0 + 1;
                float q0 = acc[mt][nt][0] * 0.125f, q1 = acc[mt][nt][1] * 0.125f;
                float c0 = g_cos[t0*DH+d0], s0 = g_sin[t0*DH+d0];
                float c1 = g_cos[t0*DH+d1], s1 = g_sin[t0*DH+d1];
                ((uint32_t*)g_qf)[((size_t)row0 * CDIM + col) >> 1] =
                    pack_h2(q0*c0 - q1*s0, q1*c1 + q0*s1);
                q0 = acc[mt][nt][2] * 0.125f; q1 = acc[mt][nt][3] * 0.125f;
                c0 = g_cos[t1*DH+d0]; s0 = g_sin[t1*DH+d0];
                c1 = g_cos[t1*DH+d1]; s1 = g_sin[t1*DH+d1];
                ((uint32_t*)g_qf)[((size_t)(row0 + 8) * CDIM + col) >> 1] =
                    pack_h2(q0*c0 - q1*s0, q1*c1 + q0*s1);
            }
        }
    }
}

__global__ void __launch_bounds__(256, 2)
proj_gemm(const __half* __restrict__ xf, const __half* __restrict__ wf,
          float* __restrict__ Ck, float* __restrict__ Cv)
{
    const int bm = blockIdx.y << 7;
    if (blockIdx.z == 0) {
        hgemm_body(xf, wf + WQ_OFF, nullptr, CDIM, CDIM, bm, blockIdx.x << 7, 1);
    } else if (blockIdx.x < 4) {
        hgemm_body(xf, wf + WK_OFF, Ck, CDIM, 512, bm, blockIdx.x << 7, 0);
    } else {
        hgemm_body(xf, wf + WV_OFF, Cv, CDIM, 512, bm, (blockIdx.x - 4) << 7, 0);
    }
}

__global__ void __launch_bounds__(256, 2)
hgemm_wc(const __half* __restrict__ A, const __half* __restrict__ B,
         float* __restrict__ C)
{
    hgemm_body(A, B, C, CDIM, CDIM, blockIdx.y << 7, blockIdx.x << 7, 0);
}

// ============================================================
// Up-projection + RoPE for k, v -> fp16. 4 tokens per CTA.
// ============================================================
__global__ void __launch_bounds__(256)
upproj_rope_kernel(const float* __restrict__ klat, const float* __restrict__ vlat,
                   const float* __restrict__ Wku,  const float* __restrict__ Wvu)
{
    const int bt0 = blockIdx.x << 2;
    __shared__ float skl[2048], svl[2048];
    __shared__ float swk[64 * 33], swv[64 * 33];
    const int tid = threadIdx.x;

    for (int u = tid; u < 512; u += 256) {
        ((float4*)skl)[u] = ((const float4*)(klat + (size_t)bt0 * 512))[u];
        ((float4*)svl)[u] = ((const float4*)(vlat + (size_t)bt0 * 512))[u];
    }
    for (int i = tid; i < 64 * 32; i += 256) {
        int d = i >> 5, l = i & 31;
        swk[d * 33 + l] = Wku[i];
        swv[d * 33 + l] = Wvu[i];
    }
    __syncthreads();

#pragma unroll
    for (int u = 0; u < 8; u++) {
        const int unit = tid + (u << 8);
        const int tok = unit >> 9;
        const int p   = unit & 511;
        const int h  = p >> 5, i = p & 31;
        const int d0 = i << 1, d1 = d0 + 1;
        const int bt = bt0 + tok;
        const int t  = bt & (T_ - 1);
        const float* kl  = &skl[(tok << 9) + (h << 5)];
        const float* vl  = &svl[(tok << 9) + (h << 5)];
        const float* wk0 = &swk[d0 * 33];
        const float* wk1 = &swk[d1 * 33];
        const float* wv0 = &swv[d0 * 33];
        const float* wv1 = &swv[d1 * 33];
        float k0 = 0.f, k1 = 0.f, v0 = 0.f, v1 = 0.f;
#pragma unroll
        for (int l = 0; l < 32; l++) {
            float klv = kl[l], vlv = vl[l];
            k0 = fmaf(klv, wk0[l], k0);
            k1 = fmaf(klv, wk1[l], k1);
            v0 = fmaf(vlv, wv0[l], v0);
            v1 = fmaf(vlv, wv1[l], v1);
        }
        const float c0 = g_cos[t * DH + d0], s0 = g_sin[t * DH + d0];
        const float c1 = g_cos[t * DH + d1], s1 = g_sin[t * DH + d1];
        const size_t pi = (((size_t)bt * H_ + h) * DH + d0) >> 1;
        ((uint32_t*)g_kf)[pi] = pack_h2(k0 * c0 - k1 * s0, k1 * c1 + k0 * s1);
        ((uint32_t*)g_vf)[pi] = pack_h2(v0, v1);
    }
}

// ============================================================
// fp16 HMMA causal flash attention (R8-validated: cp.async,
// 3-buffer single-sync KV pipeline, 2 CTAs/SM).
// ============================================================
#define AT_ROWB   144
#define AT_MAT    (64 * AT_ROWB)
#define AT_STAGE  (2 * AT_MAT)
#define AT_QOFF   (3 * AT_STAGE)
#define AT_QMAT   (128 * AT_ROWB)
#define AT_SMEM   (AT_QOFF + AT_QMAT)   // 73728

__device__ __forceinline__ void attn_load_kv(int b, int h, int kb,
                                             uint32_t sbase, int tid)
{
    const int k0 = kb << 6;
#pragma unroll
    for (int i = 0; i < 4; i++) {
        int task = tid + (i << 8);
        int op = task >> 9;
        int t2 = task & 511;
        int row = t2 >> 3, g = t2 & 7;
        const __half* base = op ? g_vf : g_kf;
        const void* src = base + ((size_t)(b * T_ + k0 + row) * H_ + h) * DH + (g << 3);
        cp16(sbase + op * AT_MAT + row * AT_ROWB + (g << 4), src);
    }
}

__global__ void __launch_bounds__(256, 2)
attn_mma_kernel()
{
    extern __shared__ __align__(128) char sm[];
    const uint32_t smb = smem_u32(sm);
    const int tid = threadIdx.x;
    const int wid = tid >> 5, lane = tid & 31;
    const int qt = gridDim.x - 1 - blockIdx.x;
    const int h = blockIdx.y, b = blockIdx.z;
    const int q0 = qt << 7;
    const int nkb = 2 * qt + 2;
    const int g = lane >> 2, tg = lane & 3;

#pragma unroll
    for (int i = 0; i < 4; i++) {
        int task = tid + (i << 8);
        int row = task >> 3, gg = task & 7;
        const void* src = g_qf + ((size_t)(b * T_ + q0 + row) * H_ + h) * DH + (gg << 3);
        cp16(smb + AT_QOFF + row * AT_ROWB + (gg << 4), src);
    }
    cp_commit();
    attn_load_kv(b, h, 0, smb, tid);
    cp_commit();
    attn_load_kv(b, h, 1, smb + AT_STAGE, tid);
    cp_commit();

    cp_wait<2>();
    __syncthreads();
    const int rA = (lane & 7) + ((lane >> 3) & 1) * 8;
    const int cA = (lane >> 4) << 3;
    uint32_t qf[4][4];
#pragma unroll
    for (int kf = 0; kf < 4; kf++) {
        uint32_t ro = (uint32_t)(wid * 16 + rA) * AT_ROWB + ((kf * 16 + cA) << 1);
        ldm_x4(qf[kf], smb + AT_QOFF + ro);
    }

    const int rB = (lane & 7) + ((lane >> 4) << 3);
    const int cB = ((lane >> 3) & 1) << 3;
    const int rV = lane & 15;
    const int cV = (lane >> 4) << 4;

    float yacc[8][4];
#pragma unroll
    for (int i = 0; i < 8; i++)
#pragma unroll
        for (int e = 0; e < 4; e++) yacc[i][e] = 0.f;
    float m0 = -1e30f, m1 = -1e30f, l0 = 0.f, l1 = 0.f;

    int bc = 0, bp = 2;
    for (int kb = 0; kb < nkb; kb++) {
        cp_wait<1>();
        __syncthreads();
        if (kb + 2 < nkb)
            attn_load_kv(b, h, kb + 2, smb + bp * AT_STAGE, tid);
        cp_commit();
        const uint32_t sb = smb + bc * AT_STAGE;
        bc = (bc == 2) ? 0 : bc + 1;
        bp = (bp == 2) ? 0 : bp + 1;

        float s[8][4];
#pragma unroll
        for (int i = 0; i < 8; i++)
#pragma unroll
            for (int e = 0; e < 4; e++) s[i][e] = 0.f;
#pragma unroll
        for (int kf = 0; kf < 4; kf++) {
#pragma unroll
            for (int nt16 = 0; nt16 < 4; nt16++) {
                uint32_t ro = (uint32_t)(nt16 * 16 + rB) * AT_ROWB + ((kf * 16 + cB) << 1);
                uint32_t bk[4];
                ldm_x4(bk, sb + ro);
                mma_f16(s[nt16 * 2],     qf[kf], &bk[0]);
                mma_f16(s[nt16 * 2 + 1], qf[kf], &bk[2]);
            }
        }

        if (kb >= 2 * qt) {
            const int row0 = q0 + wid * 16 + g;
#pragma unroll
            for (int nt = 0; nt < 8; nt++) {
                const int col0 = (kb << 6) + nt * 8 + (tg << 1);
                if (col0     > row0)     s[nt][0] = -1e30f;
                if (col0 + 1 > row0)     s[nt][1] = -1e30f;
                if (col0     > row0 + 8) s[nt][2] = -1e30f;
                if (col0 + 1 > row0 + 8) s[nt][3] = -1e30f;
            }
        }

        float mx0 = -1e30f, mx1 = -1e30f;
#pragma unroll
        for (int nt = 0; nt < 8; nt++) {
            mx0 = fmaxf(mx0, fmaxf(s[nt][0], s[nt][1]));
            mx1 = fmaxf(mx1, fmaxf(s[nt][2], s[nt][3]));
        }
        mx0 = fmaxf(mx0, __shfl_xor_sync(0xffffffffu, mx0, 1));
        mx0 = fmaxf(mx0, __shfl_xor_sync(0xffffffffu, mx0, 2));
        mx1 = fmaxf(mx1, __shfl_xor_sync(0xffffffffu, mx1, 1));
        mx1 = fmaxf(mx1, __shfl_xor_sync(0xffffffffu, mx1, 2));
        const float mn0 = fmaxf(m0, mx0), mn1 = fmaxf(m1, mx1);
        const float a0 = __expf(m0 - mn0), a1 = __expf(m1 - mn1);
        m0 = mn0; m1 = mn1;
        float r0 = 0.f, r1 = 0.f;
#pragma unroll
        for (int nt = 0; nt < 8; nt++) {
            s[nt][0] = __expf(s[nt][0] - mn0);
            s[nt][1] = __expf(s[nt][1] - mn0);
            s[nt][2] = __expf(s[nt][2] - mn1);
            s[nt][3] = __expf(s[nt][3] - mn1);
            r0 += s[nt][0] + s[nt][1];
            r1 += s[nt][2] + s[nt][3];
        }
        r0 += __shfl_xor_sync(0xffffffffu, r0, 1);
        r0 += __shfl_xor_sync(0xffffffffu, r0, 2);
        r1 += __shfl_xor_sync(0xffffffffu, r1, 1);
        r1 += __shfl_xor_sync(0xffffffffu, r1, 2);
        l0 = l0 * a0 + r0;
        l1 = l1 * a1 + r1;
#pragma unroll
        for (int i = 0; i < 8; i++) {
            yacc[i][0] *= a0; yacc[i][1] *= a0;
            yacc[i][2] *= a1; yacc[i][3] *= a1;
        }

#pragma unroll
        for (int kf = 0; kf < 4; kf++) {
            uint32_t ph[4];
            ph[0] = pack_h2(s[2*kf][0],   s[2*kf][1]);
            ph[1] = pack_h2(s[2*kf][2],   s[2*kf][3]);
            ph[2] = pack_h2(s[2*kf+1][0], s[2*kf+1][1]);
            ph[3] = pack_h2(s[2*kf+1][2], s[2*kf+1][3]);
#pragma unroll
            for (int dt = 0; dt < 4; dt++) {
                uint32_t vh[4];
                uint32_t ro = (uint32_t)(kf * 16 + rV) * AT_ROWB + dt * 32 + cV;
                ldm_x4_t(vh, sb + AT_MAT + ro);
                mma_f16(yacc[dt * 2],     ph, &vh[0]);
                mma_f16(yacc[dt * 2 + 1], ph, &vh[2]);
            }
        }
    }

    const float il0 = 1.f / l0, il1 = 1.f / l1;
    const int row0 = q0 + wid * 16 + g;
#pragma unroll
    for (int dt8 = 0; dt8 < 8; dt8++) {
        const int col = h * 64 + dt8 * 8 + (tg << 1);
        ((uint32_t*)g_yf)[((size_t)(b * T_ + row0) * CDIM + col) >> 1] =
            pack_h2(yacc[dt8][0] * il0, yacc[dt8][1] * il0);
        ((uint32_t*)g_yf)[((size_t)(b * T_ + row0 + 8) * CDIM + col) >> 1] =
            pack_h2(yacc[dt8][2] * il1, yacc[dt8][3] * il1);
    }
}

// ============================================================
// launch
// ============================================================
extern "C" void kernel_launch(void* const* d_in, const int* in_sizes, int n_in,
                              void* d_out, int out_size)
{
    const float* x   = (const float*)d_in[0];
    const float* Wq  = (const float*)d_in[1];
    const float* Wk  = (const float*)d_in[2];
    const float* Wv  = (const float*)d_in[3];
    const float* Wku = (const float*)d_in[4];
    const float* Wvu = (const float*)d_in[5];
    const float* Wc  = (const float*)d_in[6];

    float* out      = (float*)d_out;
    float* y_out    = out;
    float* klat_out = out + Y_ELEMS;
    float* vlat_out = out + Y_ELEMS + KL_ELEMS;

    __half *xf, *yf, *wf;
    cudaGetSymbolAddress((void**)&xf, g_xf);
    cudaGetSymbolAddress((void**)&yf, g_yf);
    cudaGetSymbolAddress((void**)&wf, g_wf);

    cudaFuncSetAttribute(attn_mma_kernel, cudaFuncAttributeMaxDynamicSharedMemorySize, AT_SMEM);
    cudaFuncSetAttribute(proj_gemm, cudaFuncAttributeMaxDynamicSharedMemorySize, GS_SMEM);
    cudaFuncSetAttribute(hgemm_wc, cudaFuncAttributeMaxDynamicSharedMemorySize, GS_SMEM);

    // 1. fused prep: cvt x, cvt weights, rope table
    prep_kernel<<<7680, 256>>>(x, Wq, Wk, Wv, Wc);

    // 2. projections (Wq w/ rope epilogue, k_lat, v_lat)
    dim3 gp(8, (B_ * T_) / 128, 2);
    proj_gemm<<<gp, 256, GS_SMEM>>>(xf, wf, klat_out, vlat_out);

    // 3. up-project + rope k/v
    upproj_rope_kernel<<<B_ * T_ / 4, 256>>>(klat_out, vlat_out, Wku, Wvu);

    // 4. flash attention
    dim3 ga(T_ / 128, H_, B_);
    attn_mma_kernel<<<ga, 256, AT_SMEM>>>();

    // 5. output projection
    dim3 gc(8, (B_ * T_) / 128);
    hgemm_wc<<<gc, 256, GS_SMEM>>>(yf, wf + WC_OFF, y_out);
}